// round 4
// baseline (speedup 1.0000x reference)
#include <cuda_runtime.h>
#include <cuda_fp16.h>
#include <cuda_fp8.h>

#define N_NODES 100000
#define D_FEAT  128
#define MAX_E   600000
#define NB2     592      // score kernel grid (one full wave: 148 SMs x 4 CTAs)
#define TPB     256
#define MAXC    8192
#define MARGIN  12.0f    // >> worst-case fp8 coarse-score error (~3)
#define RB      64       // rescore blocks

// Scratch (static __device__ — no allocation allowed)
__device__ __align__(128) unsigned g_h8[N_NODES * D_FEAT / 4]; // e4m3 rows, 128B each
__device__ float    g_score[MAX_E];               // coarse per-edge scores (2.4 MB)
__device__ float    g_blockmin[NB2];
__device__ int      g_cand[MAXC];
__device__ float    g_cand_score[MAXC];
__device__ float    g_rmin[RB];
__device__ int      g_ncand;

__device__ __forceinline__ __half2 fp8x2_to_h2(unsigned short v) {
    __half2_raw r = __nv_cvt_fp8x2_to_halfraw2((__nv_fp8x2_storage_t)v, __NV_E4M3);
    return *reinterpret_cast<__half2*>(&r);
}

// K1: f32 -> e4m3 conversion of h; also resets candidate counter.
__global__ void convert_kernel(const float* __restrict__ h, int n4) {
    if (blockIdx.x == 0 && threadIdx.x == 0) g_ncand = 0;
    const float4* __restrict__ h4 = (const float4*)h;
    const int stride = gridDim.x * blockDim.x;
    for (int i = blockIdx.x * blockDim.x + threadIdx.x; i < n4; i += stride) {
        float4 f = h4[i];
        unsigned lo = __nv_cvt_float2_to_fp8x2(make_float2(f.x, f.y), __NV_SATFINITE, __NV_E4M3);
        unsigned hi = __nv_cvt_float2_to_fp8x2(make_float2(f.z, f.w), __NV_SATFINITE, __NV_E4M3);
        g_h8[i] = lo | (hi << 16);
    }
}

// K2: coarse per-edge dot from fp8 rows. 8-lane group per edge; each lane
// loads one uint4 (16 fp8) of each row -> half2 FMA -> fp32 cross-lane reduce.
__global__ void score_kernel(const int* __restrict__ src,
                             const int* __restrict__ dst, int E) {
    const int lane = threadIdx.x & 31;
    const int gl   = lane & 7;
    const int gid  = (blockIdx.x * blockDim.x + threadIdx.x) >> 3;
    const int nG   = (gridDim.x * blockDim.x) >> 3;
    const uint4* __restrict__ h8 = (const uint4*)g_h8;   // row = 8 x uint4 = 128B

    float lmin = 3.4e38f;

    for (int e = gid; e < E; e += nG) {
        const int s = src[e];
        const int d = dst[e];
        uint4 ua = h8[(long long)s * 8 + gl];
        uint4 ub = h8[(long long)d * 8 + gl];
        __half2 acc = __float2half2_rn(0.f);
        const unsigned* pa = &ua.x;
        const unsigned* pb = &ub.x;
        #pragma unroll
        for (int j = 0; j < 4; j++) {
            unsigned a = pa[j], b = pb[j];
            acc = __hfma2(fp8x2_to_h2((unsigned short)(a & 0xFFFFu)),
                          fp8x2_to_h2((unsigned short)(b & 0xFFFFu)), acc);
            acc = __hfma2(fp8x2_to_h2((unsigned short)(a >> 16)),
                          fp8x2_to_h2((unsigned short)(b >> 16)), acc);
        }
        float facc = __low2float(acc) + __high2float(acc);
        #pragma unroll
        for (int off = 4; off; off >>= 1)
            facc += __shfl_xor_sync(0xFFFFFFFFu, facc, off);
        if (gl == 0) g_score[e] = facc;
        lmin = fminf(lmin, facc);
    }

    // Block min -> array (no atomics, no init kernel needed)
    __shared__ float sm[TPB / 32];
    #pragma unroll
    for (int off = 16; off; off >>= 1)
        lmin = fminf(lmin, __shfl_xor_sync(0xFFFFFFFFu, lmin, off));
    if (lane == 0) sm[threadIdx.x >> 5] = lmin;
    __syncthreads();
    if (threadIdx.x == 0) {
        float m = sm[0];
        #pragma unroll
        for (int i = 1; i < TPB / 32; i++) m = fminf(m, sm[i]);
        g_blockmin[blockIdx.x] = m;
    }
}

// K3: reduce block minima (same order in every block -> identical gmin),
// write 1.0 everywhere, collect candidates within MARGIN of coarse min.
__global__ void threshold_kernel(float* __restrict__ out, int E) {
    __shared__ float sm[TPB / 32];
    float m = 3.4e38f;
    for (int i = threadIdx.x; i < NB2; i += blockDim.x)
        m = fminf(m, g_blockmin[i]);
    #pragma unroll
    for (int off = 16; off; off >>= 1)
        m = fminf(m, __shfl_xor_sync(0xFFFFFFFFu, m, off));
    if ((threadIdx.x & 31) == 0) sm[threadIdx.x >> 5] = m;
    __syncthreads();
    float gmin = sm[0];
    #pragma unroll
    for (int i = 1; i < TPB / 32; i++) gmin = fminf(gmin, sm[i]);

    const int e = blockIdx.x * blockDim.x + threadIdx.x;
    if (e < E) {
        float sc = g_score[e];
        out[e] = 1.0f;
        if (sc <= gmin + MARGIN) {
            int idx = atomicAdd(&g_ncand, 1);
            if (idx < MAXC) g_cand[idx] = e;
        }
    }
}

// K4: exact fp32 rescore of candidates — warp per candidate, fully parallel.
// 32 lanes x float4 covers the whole 128-float row in one coalesced load.
__global__ void rescore_kernel(const float* __restrict__ h,
                               const int* __restrict__ src,
                               const int* __restrict__ dst) {
    const int lane = threadIdx.x & 31;
    const int warp = (int)((blockIdx.x * blockDim.x + threadIdx.x) >> 5);
    const int nW   = (int)((gridDim.x * blockDim.x) >> 5);
    const int nc   = min(g_ncand, MAXC);

    float wmin = 3.4e38f;
    for (int i = warp; i < nc; i += nW) {
        const int e = g_cand[i];
        float4 a = ((const float4*)(h + (long long)src[e] * D_FEAT))[lane];
        float4 b = ((const float4*)(h + (long long)dst[e] * D_FEAT))[lane];
        float acc = a.x * b.x + a.y * b.y + a.z * b.z + a.w * b.w;
        #pragma unroll
        for (int off = 16; off; off >>= 1)
            acc += __shfl_xor_sync(0xFFFFFFFFu, acc, off);
        if (lane == 0) g_cand_score[i] = acc;
        wmin = fminf(wmin, acc);
    }

    __shared__ float sm[TPB / 32];
    if (lane == 0) sm[threadIdx.x >> 5] = wmin;
    __syncthreads();
    if (threadIdx.x == 0) {
        float m = sm[0];
        #pragma unroll
        for (int i = 1; i < TPB / 32; i++) m = fminf(m, sm[i]);
        g_rmin[blockIdx.x] = m;   // always written (inf if no candidates)
    }
}

// K5: tiny — reduce RB block mins, zero the true-min edge(s).
__global__ void mark_kernel(float* __restrict__ out) {
    __shared__ float sm[TPB / 32];
    float m = 3.4e38f;
    for (int i = threadIdx.x; i < RB; i += blockDim.x)
        m = fminf(m, g_rmin[i]);
    #pragma unroll
    for (int off = 16; off; off >>= 1)
        m = fminf(m, __shfl_xor_sync(0xFFFFFFFFu, m, off));
    if ((threadIdx.x & 31) == 0) sm[threadIdx.x >> 5] = m;
    __syncthreads();
    float gm = sm[0];
    #pragma unroll
    for (int i = 1; i < TPB / 32; i++) gm = fminf(gm, sm[i]);

    const int nc = min(g_ncand, MAXC);
    for (int i = threadIdx.x; i < nc; i += blockDim.x)
        if (g_cand_score[i] == gm) out[g_cand[i]] = 0.0f;
}

extern "C" void kernel_launch(void* const* d_in, const int* in_sizes, int n_in,
                              void* d_out, int out_size) {
    const float* h   = (const float*)d_in[0];
    const int*   src = (const int*)d_in[1];
    const int*   dst = (const int*)d_in[2];
    float* out = (float*)d_out;

    const int E  = in_sizes[1];
    const int n4 = N_NODES * D_FEAT / 4;

    convert_kernel<<<NB2, TPB>>>(h, n4);
    score_kernel<<<NB2, TPB>>>(src, dst, E);
    threshold_kernel<<<(E + TPB - 1) / TPB, TPB>>>(out, E);
    rescore_kernel<<<RB, TPB>>>(h, src, dst);
    mark_kernel<<<1, TPB>>>(out);
}

// round 5
// speedup vs baseline: 1.0504x; 1.0504x over previous
#include <cuda_runtime.h>
#include <cuda_fp16.h>
#include <cuda_fp8.h>

#define N_NODES 100000
#define D_FEAT  128
#define MAX_E   600000
#define NB2     592      // convert/score grid (one full wave: 148 SMs x 4 CTAs)
#define TPB     256
#define MAXC    8192
#define MARGIN  12.0f    // >> worst-case fp8+half coarse-score error (~3.5)

// Scratch (static __device__ — no allocation allowed)
__device__ __align__(128) unsigned g_h8[N_NODES * D_FEAT / 4]; // e4m3 rows, 128B each
__device__ float    g_score[MAX_E];               // coarse per-edge scores (2.4 MB)
__device__ float    g_blockmin[NB2];
__device__ int      g_cand[MAXC];
__device__ float    g_cand_score[MAXC];
__device__ int      g_ncand;
__device__ int      g_done;

__device__ __forceinline__ __half2 fp8x2_to_h2(unsigned short v) {
    __half2_raw r = __nv_cvt_fp8x2_to_halfraw2((__nv_fp8x2_storage_t)v, __NV_E4M3);
    return *reinterpret_cast<__half2*>(&r);
}

// K1: f32 -> e4m3 conversion of h; also resets counters (graph-replay safe:
// this kernel runs first on every call).
__global__ void convert_kernel(const float* __restrict__ h, int n4) {
    if (blockIdx.x == 0 && threadIdx.x == 0) { g_ncand = 0; g_done = 0; }
    const float4* __restrict__ h4 = (const float4*)h;
    const int stride = gridDim.x * blockDim.x;
    for (int i = blockIdx.x * blockDim.x + threadIdx.x; i < n4; i += stride) {
        float4 f = h4[i];
        unsigned lo = __nv_cvt_float2_to_fp8x2(make_float2(f.x, f.y), __NV_SATFINITE, __NV_E4M3);
        unsigned hi = __nv_cvt_float2_to_fp8x2(make_float2(f.z, f.w), __NV_SATFINITE, __NV_E4M3);
        g_h8[i] = lo | (hi << 16);
    }
}

// K2: coarse per-edge dot from fp8 rows. 8-lane group per edge; each lane
// loads one uint4 (16 fp8) of each row -> half2 FMA -> fp32 cross-lane reduce.
__global__ void score_kernel(const int* __restrict__ src,
                             const int* __restrict__ dst, int E) {
    const int lane = threadIdx.x & 31;
    const int gl   = lane & 7;
    const int gid  = (blockIdx.x * blockDim.x + threadIdx.x) >> 3;
    const int nG   = (gridDim.x * blockDim.x) >> 3;
    const uint4* __restrict__ h8 = (const uint4*)g_h8;   // row = 8 x uint4 = 128B

    float lmin = 3.4e38f;

    for (int e = gid; e < E; e += nG) {
        const int s = src[e];
        const int d = dst[e];
        uint4 ua = h8[(long long)s * 8 + gl];
        uint4 ub = h8[(long long)d * 8 + gl];
        __half2 acc = __float2half2_rn(0.f);
        const unsigned* pa = &ua.x;
        const unsigned* pb = &ub.x;
        #pragma unroll
        for (int j = 0; j < 4; j++) {
            unsigned a = pa[j], b = pb[j];
            acc = __hfma2(fp8x2_to_h2((unsigned short)(a & 0xFFFFu)),
                          fp8x2_to_h2((unsigned short)(b & 0xFFFFu)), acc);
            acc = __hfma2(fp8x2_to_h2((unsigned short)(a >> 16)),
                          fp8x2_to_h2((unsigned short)(b >> 16)), acc);
        }
        float facc = __low2float(acc) + __high2float(acc);
        #pragma unroll
        for (int off = 4; off; off >>= 1)
            facc += __shfl_xor_sync(0xFFFFFFFFu, facc, off);
        if (gl == 0) g_score[e] = facc;
        lmin = fminf(lmin, facc);
    }

    // Block min -> array (no atomics, no init kernel needed)
    __shared__ float sm[TPB / 32];
    #pragma unroll
    for (int off = 16; off; off >>= 1)
        lmin = fminf(lmin, __shfl_xor_sync(0xFFFFFFFFu, lmin, off));
    if (lane == 0) sm[threadIdx.x >> 5] = lmin;
    __syncthreads();
    if (threadIdx.x == 0) {
        float m = sm[0];
        #pragma unroll
        for (int i = 1; i < TPB / 32; i++) m = fminf(m, sm[i]);
        g_blockmin[blockIdx.x] = m;
    }
}

// K3 (fused): every block reduces the 592 block-minima (L2-cached, ~free),
// writes out=1, collects candidates within MARGIN; the LAST block to finish
// rescales candidates exactly in fp32 and zeroes the true argmin edge(s).
__global__ void finalize_kernel(const float* __restrict__ h,
                                const int* __restrict__ src,
                                const int* __restrict__ dst,
                                float* __restrict__ out, int E) {
    __shared__ float sm[TPB / 32];
    __shared__ bool s_last;
    const int lane = threadIdx.x & 31;
    const int wid  = threadIdx.x >> 5;

    // Redundant per-block gmin reduce (identical order -> identical result).
    float m = 3.4e38f;
    for (int i = threadIdx.x; i < NB2; i += blockDim.x)
        m = fminf(m, g_blockmin[i]);
    #pragma unroll
    for (int off = 16; off; off >>= 1)
        m = fminf(m, __shfl_xor_sync(0xFFFFFFFFu, m, off));
    if (lane == 0) sm[wid] = m;
    __syncthreads();
    float gmin = sm[0];
    #pragma unroll
    for (int i = 1; i < TPB / 32; i++) gmin = fminf(gmin, sm[i]);
    __syncthreads();   // sm[] reused below

    const int e = blockIdx.x * blockDim.x + threadIdx.x;
    if (e < E) {
        out[e] = 1.0f;
        if (g_score[e] <= gmin + MARGIN) {
            int idx = atomicAdd(&g_ncand, 1);
            if (idx < MAXC) g_cand[idx] = e;
        }
    }

    // Completion protocol: last block does the exact refine.
    __threadfence();
    if (threadIdx.x == 0) {
        int t = atomicAdd(&g_done, 1);
        s_last = (t == (int)gridDim.x - 1);
    }
    __syncthreads();
    if (!s_last) return;

    // --- Last block only: exact fp32 rescore of candidates ---
    const int nc = min(g_ncand, MAXC);

    float wmin = 3.4e38f;
    for (int i = wid; i < nc; i += TPB / 32) {     // warp per candidate
        const int ce = g_cand[i];
        float4 a = ((const float4*)(h + (long long)src[ce] * D_FEAT))[lane];
        float4 b = ((const float4*)(h + (long long)dst[ce] * D_FEAT))[lane];
        float acc = a.x * b.x + a.y * b.y + a.z * b.z + a.w * b.w;
        #pragma unroll
        for (int off = 16; off; off >>= 1)
            acc += __shfl_xor_sync(0xFFFFFFFFu, acc, off);
        if (lane == 0) g_cand_score[i] = acc;
        wmin = fminf(wmin, acc);
    }
    if (lane == 0) sm[wid] = wmin;
    __syncthreads();
    float gm = sm[0];
    #pragma unroll
    for (int i = 1; i < TPB / 32; i++) gm = fminf(gm, sm[i]);

    for (int i = threadIdx.x; i < nc; i += blockDim.x)
        if (g_cand_score[i] == gm) out[g_cand[i]] = 0.0f;
}

extern "C" void kernel_launch(void* const* d_in, const int* in_sizes, int n_in,
                              void* d_out, int out_size) {
    const float* h   = (const float*)d_in[0];
    const int*   src = (const int*)d_in[1];
    const int*   dst = (const int*)d_in[2];
    float* out = (float*)d_out;

    const int E  = in_sizes[1];
    const int n4 = N_NODES * D_FEAT / 4;

    convert_kernel<<<NB2, TPB>>>(h, n4);
    score_kernel<<<NB2, TPB>>>(src, dst, E);
    finalize_kernel<<<(E + TPB - 1) / TPB, TPB>>>(h, src, dst, out, E);
}